// round 2
// baseline (speedup 1.0000x reference)
#include <cuda_runtime.h>
#include <cuda_bf16.h>

#define BB 2
#define CC 256
#define HH 64
#define WWD 64
#define LL 4096
#define NN 16
#define RR 64

// ---------------- static device scratch (no allocations) ----------------
__device__ float4 g_A4   [CC*NN/4];          // A = -exp(A_log), (c,n)
__device__ float  g_delta[BB*LL*CC];         // (b,p,c)
__device__ float  g_u    [BB*LL*CC];         // delta * x
__device__ float4 g_Bm4  [BB*LL*NN/4];       // (b,p,n)
__device__ float4 g_Cm4  [BB*LL*NN/4];
__device__ float  g_rs   [BB*RR*CC];         // row delta sums
__device__ float  g_cs   [BB*RR*CC];         // col delta sums
__device__ float4 g_ef4  [BB*RR*CC*NN/4];    // row fwd local end states
__device__ float4 g_eb4  [BB*RR*CC*NN/4];    // row bwd local end states
__device__ float4 g_ec4  [BB*RR*CC*NN/4];    // col fwd local end states
__device__ float4 g_c14  [BB*RR*CC*NN/4];    // carries per chunk, dir 1..4
__device__ float4 g_c24  [BB*RR*CC*NN/4];
__device__ float4 g_c34  [BB*RR*CC*NN/4];
__device__ float4 g_c44  [BB*RR*CC*NN/4];
__device__ float  g_y13  [BB*LL*CC];         // y1 + y3
__device__ float  g_y2   [BB*LL*CC];
__device__ float  g_y4   [BB*LL*CC];

// ---------------- prep: A = -exp(A_log) ----------------
__global__ void k_prep(const float* __restrict__ A_log) {
    int i = blockIdx.x * blockDim.x + threadIdx.x;
    if (i < CC*NN) ((float*)g_A4)[i] = -expf(A_log[i]);
}

// ---------------- small GEMM: Bm = x@W_B, Cm = x@W_C ----------------
// x[m,k] = F[b, k, p] with m = b*LL + p. Grid: 128 blocks of 64 rows.
__global__ void __launch_bounds__(256) k_gemm_bc(
    const float* __restrict__ F,
    const float* __restrict__ W_B,
    const float* __restrict__ W_C)
{
    __shared__ float Ws[64][32];
    __shared__ float xs[64][64];
    int t = threadIdx.x;
    int m0 = blockIdx.x * 64;
    int b = m0 / LL;
    int pbase = m0 % LL;
    int n = t & 31;
    int tw = t >> 5;               // 0..7
    float acc[8] = {0,0,0,0,0,0,0,0};

    for (int kc = 0; kc < 4; kc++) {
        int k0 = kc * 64;
        __syncthreads();
        #pragma unroll
        for (int i = 0; i < 8; i++) {       // Ws: 64x32
            int e = t + i*256;
            int kk = e >> 5, nn = e & 31;
            int k = k0 + kk;
            Ws[kk][nn] = (nn < 16) ? W_B[k*16 + nn] : W_C[k*16 + (nn-16)];
        }
        #pragma unroll
        for (int i = 0; i < 16; i++) {      // xs: 64x64
            int e = t + i*256;
            int m = e & 63, kk = e >> 6;
            xs[kk][m] = F[(size_t)b*CC*LL + (size_t)(k0+kk)*LL + pbase + m];
        }
        __syncthreads();
        for (int kk = 0; kk < 64; kk++) {
            float w = Ws[kk][n];
            #pragma unroll
            for (int mi = 0; mi < 8; mi++)
                acc[mi] = fmaf(xs[kk][tw + mi*8], w, acc[mi]);
        }
    }
    float* gBm = (float*)g_Bm4;
    float* gCm = (float*)g_Cm4;
    #pragma unroll
    for (int mi = 0; mi < 8; mi++) {
        int m = m0 + tw + mi*8;
        if (n < 16) gBm[m*NN + n] = acc[mi];
        else        gCm[m*NN + (n-16)] = acc[mi];
    }
}

// ---------------- big GEMM: xw = x@W_delta + b_delta -> delta, u ----------------
__global__ void __launch_bounds__(256) k_gemm_delta(
    const float* __restrict__ F,
    const float* __restrict__ Wd,
    const float* __restrict__ bd)
{
    __shared__ float As[32][64];
    __shared__ float Bs[32][64];
    int t = threadIdx.x;
    int m0 = blockIdx.x * 64;
    int n0 = blockIdx.y * 64;
    int b = m0 / LL;
    int pbase = m0 % LL;
    int tm0 = (t & 15) * 4;
    int tn0 = (t >> 4) * 4;
    float acc[4][4] = {};

    for (int kc = 0; kc < 8; kc++) {
        int k0 = kc * 32;
        __syncthreads();
        #pragma unroll
        for (int i = 0; i < 8; i++) {
            int e = t + i*256;
            int m = e & 63, k = e >> 6;
            As[k][m] = F[(size_t)b*CC*LL + (size_t)(k0+k)*LL + pbase + m];
            Bs[k][m] = Wd[(k0+k)*CC + n0 + m];
        }
        __syncthreads();
        #pragma unroll
        for (int k = 0; k < 32; k++) {
            float4 a4 = *(const float4*)&As[k][tm0];
            float4 b4 = *(const float4*)&Bs[k][tn0];
            float av[4] = {a4.x, a4.y, a4.z, a4.w};
            float bv[4] = {b4.x, b4.y, b4.z, b4.w};
            #pragma unroll
            for (int i = 0; i < 4; i++)
                #pragma unroll
                for (int j = 0; j < 4; j++)
                    acc[i][j] = fmaf(av[i], bv[j], acc[i][j]);
        }
    }
    #pragma unroll
    for (int i = 0; i < 4; i++) {
        int p = pbase + tm0 + i;
        size_t mg = (size_t)(m0 + tm0 + i);
        #pragma unroll
        for (int j = 0; j < 4; j++) {
            int c = n0 + tn0 + j;
            float xw = acc[i][j] + bd[c];
            // numerically stable softplus
            float sp = (xw > 0.f) ? xw + log1pf(__expf(-xw)) : log1pf(__expf(xw));
            float xv = F[(size_t)b*CC*LL + (size_t)c*LL + p];
            g_delta[mg*CC + c] = sp;
            g_u[mg*CC + c]     = sp * xv;
        }
    }
}

// ---------------- pass1: per-chunk local end states + delta sums ----------------
// blocks [0, 2*BB*RR): first BB*RR = row chunks, rest = column chunks.
__global__ void __launch_bounds__(256, 2) k_pass1() {
    int blk = blockIdx.x;
    int c = threadIdx.x;
    const float* gA = (const float*)g_A4;
    const float* gBm = (const float*)g_Bm4;
    float Acn[NN];
    #pragma unroll
    for (int n = 0; n < NN; n++) Acn[n] = gA[c*NN + n];

    if (blk < BB*RR) {
        int b = blk / RR, r = blk % RR;
        float ef[NN], eb[NN], Pp[NN];
        #pragma unroll
        for (int n = 0; n < NN; n++) { ef[n]=0.f; eb[n]=0.f; Pp[n]=1.f; }
        float rs = 0.f;
        for (int ts = 0; ts < 64; ts++) {
            int p = r*64 + ts;
            size_t idx = ((size_t)(b*LL + p))*CC + c;
            float d = g_delta[idx];
            float uu = g_u[idx];
            rs += d;
            float bm[NN];
            {
                int base4 = (b*LL + p)*4;
                #pragma unroll
                for (int j = 0; j < 4; j++) {
                    float4 v = g_Bm4[base4 + j];
                    bm[4*j]=v.x; bm[4*j+1]=v.y; bm[4*j+2]=v.z; bm[4*j+3]=v.w;
                }
            }
            #pragma unroll
            for (int n = 0; n < NN; n++) {
                float a = __expf(d * Acn[n]);
                float w = uu * bm[n];
                eb[n] = fmaf(w, Pp[n], eb[n]);   // e_b = sum w_t * prod_{s<t} a_s
                Pp[n] *= a;
                ef[n] = fmaf(a, ef[n], w);       // e_f fwd recurrence
            }
        }
        float* gef = (float*)g_ef4;
        float* geb = (float*)g_eb4;
        size_t base = ((size_t)(b*RR + r)*CC + c)*NN;
        #pragma unroll
        for (int n = 0; n < NN; n++) { gef[base+n] = ef[n]; geb[base+n] = eb[n]; }
        g_rs[(b*RR + r)*CC + c] = rs;
    } else {
        int blk2 = blk - BB*RR;
        int b = blk2 / RR, w = blk2 % RR;
        float ec[NN];
        #pragma unroll
        for (int n = 0; n < NN; n++) ec[n] = 0.f;
        float cs = 0.f;
        for (int h = 0; h < 64; h++) {
            int p = h*64 + w;
            size_t idx = ((size_t)(b*LL + p))*CC + c;
            float d = g_delta[idx];
            float uu = g_u[idx];
            cs += d;
            float bm[NN];
            {
                int base4 = (b*LL + p)*4;
                #pragma unroll
                for (int j = 0; j < 4; j++) {
                    float4 v = g_Bm4[base4 + j];
                    bm[4*j]=v.x; bm[4*j+1]=v.y; bm[4*j+2]=v.z; bm[4*j+3]=v.w;
                }
            }
            #pragma unroll
            for (int n = 0; n < NN; n++) {
                float a = __expf(d * Acn[n]);
                float wv = uu * bm[n];
                ec[n] = fmaf(a, ec[n], wv);
            }
        }
        float* gec = (float*)g_ec4;
        size_t base = ((size_t)(b*RR + w)*CC + c)*NN;
        #pragma unroll
        for (int n = 0; n < NN; n++) gec[base+n] = ec[n];
        g_cs[(b*RR + w)*CC + c] = cs;
    }
}

// ---------------- mid: inter-chunk carry scans (serial over 64 chunks) ----------------
__global__ void k_mid() {
    int g = blockIdx.x * blockDim.x + threadIdx.x;   // BB*CC*NN = 8192
    int b = g / (CC*NN);
    int cn = g % (CC*NN);
    int c = cn / NN;
    float Acn = ((const float*)g_A4)[cn];
    const float* gef = (const float*)g_ef4;
    const float* geb = (const float*)g_eb4;
    const float* gec = (const float*)g_ec4;
    float* gc1 = (float*)g_c14;
    float* gc2 = (float*)g_c24;
    float* gc3 = (float*)g_c34;
    float* gc4 = (float*)g_c44;
    size_t ebase = (size_t)b*RR*CC*NN + cn;
    int rbase = b*RR*CC + c;

    float cur = 0.f;                       // dir1: rows ascending, carry from r-1
    for (int r = 0; r < RR; r++) {
        size_t ei = ebase + (size_t)r*CC*NN;
        gc1[ei] = cur;
        float G = __expf(Acn * g_rs[rbase + r*CC]);
        cur = fmaf(G, cur, gef[ei]);
    }
    float cur2 = 0.f, cur3 = 0.f;          // dir2 (bwd local), dir3 (fwd local), rows descending
    for (int r = RR-1; r >= 0; r--) {
        size_t ei = ebase + (size_t)r*CC*NN;
        gc2[ei] = cur2;
        gc3[ei] = cur3;
        float G = __expf(Acn * g_rs[rbase + r*CC]);
        cur2 = fmaf(G, cur2, geb[ei]);
        cur3 = fmaf(G, cur3, gef[ei]);
    }
    float cur4 = 0.f;                      // dir4: cols descending, fwd-in-col local
    for (int w = RR-1; w >= 0; w--) {
        size_t ei = ebase + (size_t)w*CC*NN;
        gc4[ei] = cur4;
        float G = __expf(Acn * g_cs[rbase + w*CC]);
        cur4 = fmaf(G, cur4, gec[ei]);
    }
}

// ---------------- pass2: local scans with carries, emit y contributions ----------------
__global__ void __launch_bounds__(256, 2) k_pass2() {
    int blk = blockIdx.x;
    int c = threadIdx.x;
    const float* gA = (const float*)g_A4;
    float Acn[NN];
    #pragma unroll
    for (int n = 0; n < NN; n++) Acn[n] = gA[c*NN + n];

    if (blk < BB*RR) {
        int b = blk / RR, r = blk % RR;
        const float* gc1 = (const float*)g_c14;
        const float* gc2 = (const float*)g_c24;
        const float* gc3 = (const float*)g_c34;
        size_t cbase = ((size_t)(b*RR + r)*CC + c)*NN;
        float h1[NN], h3[NN];
        #pragma unroll
        for (int n = 0; n < NN; n++) { h1[n] = gc1[cbase+n]; h3[n] = gc3[cbase+n]; }
        // ascending: dir1 + dir3
        for (int ts = 0; ts < 64; ts++) {
            int p = r*64 + ts;
            size_t idx = ((size_t)(b*LL + p))*CC + c;
            float d = g_delta[idx];
            float uu = g_u[idx];
            float bm[NN], cm[NN];
            {
                int base4 = (b*LL + p)*4;
                #pragma unroll
                for (int j = 0; j < 4; j++) {
                    float4 v = g_Bm4[base4 + j];
                    bm[4*j]=v.x; bm[4*j+1]=v.y; bm[4*j+2]=v.z; bm[4*j+3]=v.w;
                    float4 v2 = g_Cm4[base4 + j];
                    cm[4*j]=v2.x; cm[4*j+1]=v2.y; cm[4*j+2]=v2.z; cm[4*j+3]=v2.w;
                }
            }
            float y = 0.f;
            #pragma unroll
            for (int n = 0; n < NN; n++) {
                float a = __expf(d * Acn[n]);
                float w = uu * bm[n];
                h1[n] = fmaf(a, h1[n], w);
                h3[n] = fmaf(a, h3[n], w);
                y = fmaf(h1[n] + h3[n], cm[n], y);
            }
            g_y13[idx] = y;
        }
        // descending: dir2
        float h2[NN];
        #pragma unroll
        for (int n = 0; n < NN; n++) h2[n] = gc2[cbase+n];
        for (int ts = 63; ts >= 0; ts--) {
            int p = r*64 + ts;
            size_t idx = ((size_t)(b*LL + p))*CC + c;
            float d = g_delta[idx];
            float uu = g_u[idx];
            float bm[NN], cm[NN];
            {
                int base4 = (b*LL + p)*4;
                #pragma unroll
                for (int j = 0; j < 4; j++) {
                    float4 v = g_Bm4[base4 + j];
                    bm[4*j]=v.x; bm[4*j+1]=v.y; bm[4*j+2]=v.z; bm[4*j+3]=v.w;
                    float4 v2 = g_Cm4[base4 + j];
                    cm[4*j]=v2.x; cm[4*j+1]=v2.y; cm[4*j+2]=v2.z; cm[4*j+3]=v2.w;
                }
            }
            float y = 0.f;
            #pragma unroll
            for (int n = 0; n < NN; n++) {
                float a = __expf(d * Acn[n]);
                float w = uu * bm[n];
                h2[n] = fmaf(a, h2[n], w);
                y = fmaf(h2[n], cm[n], y);
            }
            g_y2[idx] = y;
        }
    } else {
        int blk2 = blk - BB*RR;
        int b = blk2 / RR, w = blk2 % RR;
        const float* gc4 = (const float*)g_c44;
        size_t cbase = ((size_t)(b*RR + w)*CC + c)*NN;
        float h4[NN];
        #pragma unroll
        for (int n = 0; n < NN; n++) h4[n] = gc4[cbase+n];
        for (int h = 0; h < 64; h++) {
            int p = h*64 + w;
            size_t idx = ((size_t)(b*LL + p))*CC + c;
            float d = g_delta[idx];
            float uu = g_u[idx];
            float bm[NN], cm[NN];
            {
                int base4 = (b*LL + p)*4;
                #pragma unroll
                for (int j = 0; j < 4; j++) {
                    float4 v = g_Bm4[base4 + j];
                    bm[4*j]=v.x; bm[4*j+1]=v.y; bm[4*j+2]=v.z; bm[4*j+3]=v.w;
                    float4 v2 = g_Cm4[base4 + j];
                    cm[4*j]=v2.x; cm[4*j+1]=v2.y; cm[4*j+2]=v2.z; cm[4*j+3]=v2.w;
                }
            }
            float y = 0.f;
            #pragma unroll
            for (int n = 0; n < NN; n++) {
                float a = __expf(d * Acn[n]);
                float wv = uu * bm[n];
                h4[n] = fmaf(a, h4[n], wv);
                y = fmaf(h4[n], cm[n], y);
            }
            g_y4[idx] = y;
        }
    }
}

// ---------------- final: combine, add x*D, transpose (p,c) -> (c,p) ----------------
__global__ void k_final(const float* __restrict__ F,
                        const float* __restrict__ Dv,
                        float* __restrict__ out)
{
    __shared__ float tile[32][33];
    int p0 = blockIdx.x * 32;
    int c0 = blockIdx.y * 32;
    int b = blockIdx.z;
    int tx = threadIdx.x, ty = threadIdx.y;   // (32, 8)
    #pragma unroll
    for (int i = 0; i < 4; i++) {
        int p = p0 + ty + i*8;
        size_t idx = ((size_t)(b*LL + p))*CC + c0 + tx;
        tile[ty + i*8][tx] = g_y13[idx] + g_y2[idx] + g_y4[idx];
    }
    __syncthreads();
    #pragma unroll
    for (int i = 0; i < 4; i++) {
        int cc = c0 + ty + i*8;
        int p = p0 + tx;
        size_t o = (size_t)b*CC*LL + (size_t)cc*LL + p;
        out[o] = 0.25f * tile[tx][ty + i*8] + F[o] * Dv[cc];
    }
}

// ---------------- launch ----------------
extern "C" void kernel_launch(void* const* d_in, const int* in_sizes, int n_in,
                              void* d_out, int out_size) {
    const float* F     = (const float*)d_in[0];
    const float* A_log = (const float*)d_in[1];
    const float* Dv    = (const float*)d_in[2];
    const float* Wd    = (const float*)d_in[3];
    const float* bd    = (const float*)d_in[4];
    const float* WB    = (const float*)d_in[5];
    const float* WC    = (const float*)d_in[6];
    float* out = (float*)d_out;

    k_prep<<<16, 256>>>(A_log);
    k_gemm_bc<<<BB*LL/64, 256>>>(F, WB, WC);
    {
        dim3 gd(BB*LL/64, CC/64);
        k_gemm_delta<<<gd, 256>>>(F, Wd, bd);
    }
    k_pass1<<<2*BB*RR, 256>>>();
    k_mid<<<BB*CC*NN/256, 256>>>();
    k_pass2<<<2*BB*RR, 256>>>();
    k_final<<<dim3(LL/32, CC/32, BB), dim3(32, 8)>>>(F, Dv, out);
}

// round 3
// speedup vs baseline: 1.0840x; 1.0840x over previous
#include <cuda_runtime.h>
#include <cuda_bf16.h>

#define BB 2
#define CC 256
#define LL 4096
#define NN 16
#define RR 64
#define NH 8    // n-values per thread (n split across lane pairs)

// ---------------- static device scratch (no allocations) ----------------
__device__ float4 g_A4   [CC*NN/4];          // A = -exp(A_log), (c,n)
__device__ float2 g_du   [BB*LL*CC];         // (delta, delta*x) packed
__device__ float4 g_Bm4  [BB*LL*NN/4];       // (b,p,n)
__device__ float4 g_Cm4  [BB*LL*NN/4];
__device__ float  g_rs   [BB*RR*CC];         // row delta sums
__device__ float  g_cs   [BB*RR*CC];         // col delta sums
__device__ float4 g_ef4  [BB*RR*CC*NN/4];    // row fwd local end states
__device__ float4 g_eb4  [BB*RR*CC*NN/4];    // row bwd local end states
__device__ float4 g_ec4  [BB*RR*CC*NN/4];    // col fwd local end states
__device__ float4 g_c14  [BB*RR*CC*NN/4];    // carries per chunk, dir 1..4
__device__ float4 g_c24  [BB*RR*CC*NN/4];
__device__ float4 g_c34  [BB*RR*CC*NN/4];
__device__ float4 g_c44  [BB*RR*CC*NN/4];
__device__ float  g_y13  [BB*LL*CC];         // y1+y2+y3 (y2 accumulated in-place)
__device__ float  g_y4   [BB*LL*CC];

// ---------------- prep: A = -exp(A_log) ----------------
__global__ void k_prep(const float* __restrict__ A_log) {
    int i = blockIdx.x * blockDim.x + threadIdx.x;
    if (i < CC*NN) ((float*)g_A4)[i] = -expf(A_log[i]);
}

// ---------------- small GEMM: Bm = x@W_B, Cm = x@W_C ----------------
__global__ void __launch_bounds__(256) k_gemm_bc(
    const float* __restrict__ F,
    const float* __restrict__ W_B,
    const float* __restrict__ W_C)
{
    __shared__ float Ws[64][32];
    __shared__ float xs[64][64];
    int t = threadIdx.x;
    int m0 = blockIdx.x * 64;
    int b = m0 / LL;
    int pbase = m0 % LL;
    int n = t & 31;
    int tw = t >> 5;
    float acc[8] = {0,0,0,0,0,0,0,0};

    for (int kc = 0; kc < 4; kc++) {
        int k0 = kc * 64;
        __syncthreads();
        #pragma unroll
        for (int i = 0; i < 8; i++) {
            int e = t + i*256;
            int kk = e >> 5, nn = e & 31;
            int k = k0 + kk;
            Ws[kk][nn] = (nn < 16) ? W_B[k*16 + nn] : W_C[k*16 + (nn-16)];
        }
        #pragma unroll
        for (int i = 0; i < 16; i++) {
            int e = t + i*256;
            int m = e & 63, kk = e >> 6;
            xs[kk][m] = F[(size_t)b*CC*LL + (size_t)(k0+kk)*LL + pbase + m];
        }
        __syncthreads();
        for (int kk = 0; kk < 64; kk++) {
            float w = Ws[kk][n];
            #pragma unroll
            for (int mi = 0; mi < 8; mi++)
                acc[mi] = fmaf(xs[kk][tw + mi*8], w, acc[mi]);
        }
    }
    float* gBm = (float*)g_Bm4;
    float* gCm = (float*)g_Cm4;
    #pragma unroll
    for (int mi = 0; mi < 8; mi++) {
        int m = m0 + tw + mi*8;
        if (n < 16) gBm[m*NN + n] = acc[mi];
        else        gCm[m*NN + (n-16)] = acc[mi];
    }
}

// ---------------- big GEMM: xw = x@W_delta + b_delta -> (delta, delta*x) ----------------
__global__ void __launch_bounds__(256) k_gemm_delta(
    const float* __restrict__ F,
    const float* __restrict__ Wd,
    const float* __restrict__ bd)
{
    __shared__ float As[32][64];
    __shared__ float Bs[32][64];
    int t = threadIdx.x;
    int m0 = blockIdx.x * 64;
    int n0 = blockIdx.y * 64;
    int b = m0 / LL;
    int pbase = m0 % LL;
    int tm0 = (t & 15) * 4;
    int tn0 = (t >> 4) * 4;
    float acc[4][4] = {};

    for (int kc = 0; kc < 8; kc++) {
        int k0 = kc * 32;
        __syncthreads();
        #pragma unroll
        for (int i = 0; i < 8; i++) {
            int e = t + i*256;
            int m = e & 63, k = e >> 6;
            As[k][m] = F[(size_t)b*CC*LL + (size_t)(k0+k)*LL + pbase + m];
            Bs[k][m] = Wd[(k0+k)*CC + n0 + m];
        }
        __syncthreads();
        #pragma unroll
        for (int k = 0; k < 32; k++) {
            float4 a4 = *(const float4*)&As[k][tm0];
            float4 b4 = *(const float4*)&Bs[k][tn0];
            float av[4] = {a4.x, a4.y, a4.z, a4.w};
            float bv[4] = {b4.x, b4.y, b4.z, b4.w};
            #pragma unroll
            for (int i = 0; i < 4; i++)
                #pragma unroll
                for (int j = 0; j < 4; j++)
                    acc[i][j] = fmaf(av[i], bv[j], acc[i][j]);
        }
    }
    #pragma unroll
    for (int i = 0; i < 4; i++) {
        int p = pbase + tm0 + i;
        size_t mg = (size_t)(m0 + tm0 + i);
        #pragma unroll
        for (int j = 0; j < 4; j++) {
            int c = n0 + tn0 + j;
            float xw = acc[i][j] + bd[c];
            float sp = (xw > 0.f) ? xw + log1pf(__expf(-xw)) : log1pf(__expf(xw));
            float xv = F[(size_t)b*CC*LL + (size_t)c*LL + p];
            g_du[mg*CC + c] = make_float2(sp, sp * xv);
        }
    }
}

// ---------------- pass1: per-chunk local end states + delta sums ----------------
// grid = 1024 blocks: [0,512) rows, [512,1024) cols. Each block: 128 c x 2 n-halves.
__global__ void __launch_bounds__(256, 3) k_pass1() {
    int blk = blockIdx.x;
    bool isCol = blk >= BB*RR*2;
    int bid = isCol ? blk - BB*RR*2 : blk;
    int b = bid / (RR*2);
    int rem = bid % (RR*2);
    int chunk = rem >> 1;
    int cg = rem & 1;
    int half = threadIdx.x & 1;
    int c = cg*128 + (threadIdx.x >> 1);

    float Acn[NH];
    {
        float4 a0 = g_A4[c*4 + half*2];
        float4 a1 = g_A4[c*4 + half*2 + 1];
        Acn[0]=a0.x; Acn[1]=a0.y; Acn[2]=a0.z; Acn[3]=a0.w;
        Acn[4]=a1.x; Acn[5]=a1.y; Acn[6]=a1.z; Acn[7]=a1.w;
    }

    if (!isCol) {
        float ef[NH], eb[NH], Pp[NH];
        #pragma unroll
        for (int n = 0; n < NH; n++) { ef[n]=0.f; eb[n]=0.f; Pp[n]=1.f; }
        float rs = 0.f;
        #pragma unroll 2
        for (int ts = 0; ts < 64; ts++) {
            int p = chunk*64 + ts;
            size_t idx = ((size_t)(b*LL + p))*CC + c;
            float2 du = g_du[idx];
            float d = du.x, uu = du.y;
            rs += d;
            float bm[NH];
            {
                float4 v0 = g_Bm4[(b*LL + p)*4 + half*2];
                float4 v1 = g_Bm4[(b*LL + p)*4 + half*2 + 1];
                bm[0]=v0.x; bm[1]=v0.y; bm[2]=v0.z; bm[3]=v0.w;
                bm[4]=v1.x; bm[5]=v1.y; bm[6]=v1.z; bm[7]=v1.w;
            }
            #pragma unroll
            for (int n = 0; n < NH; n++) {
                float a = __expf(d * Acn[n]);
                float w = uu * bm[n];
                eb[n] = fmaf(w, Pp[n], eb[n]);
                Pp[n] *= a;
                ef[n] = fmaf(a, ef[n], w);
            }
        }
        int i4 = ((b*RR + chunk)*CC + c)*4 + half*2;
        g_ef4[i4]   = make_float4(ef[0],ef[1],ef[2],ef[3]);
        g_ef4[i4+1] = make_float4(ef[4],ef[5],ef[6],ef[7]);
        g_eb4[i4]   = make_float4(eb[0],eb[1],eb[2],eb[3]);
        g_eb4[i4+1] = make_float4(eb[4],eb[5],eb[6],eb[7]);
        if (half == 0) g_rs[(b*RR + chunk)*CC + c] = rs;
    } else {
        float ec[NH];
        #pragma unroll
        for (int n = 0; n < NH; n++) ec[n] = 0.f;
        float cs = 0.f;
        #pragma unroll 2
        for (int h = 0; h < 64; h++) {
            int p = h*64 + chunk;
            size_t idx = ((size_t)(b*LL + p))*CC + c;
            float2 du = g_du[idx];
            float d = du.x, uu = du.y;
            cs += d;
            float bm[NH];
            {
                float4 v0 = g_Bm4[(b*LL + p)*4 + half*2];
                float4 v1 = g_Bm4[(b*LL + p)*4 + half*2 + 1];
                bm[0]=v0.x; bm[1]=v0.y; bm[2]=v0.z; bm[3]=v0.w;
                bm[4]=v1.x; bm[5]=v1.y; bm[6]=v1.z; bm[7]=v1.w;
            }
            #pragma unroll
            for (int n = 0; n < NH; n++) {
                float a = __expf(d * Acn[n]);
                float wv = uu * bm[n];
                ec[n] = fmaf(a, ec[n], wv);
            }
        }
        int i4 = ((b*RR + chunk)*CC + c)*4 + half*2;
        g_ec4[i4]   = make_float4(ec[0],ec[1],ec[2],ec[3]);
        g_ec4[i4+1] = make_float4(ec[4],ec[5],ec[6],ec[7]);
        if (half == 0) g_cs[(b*RR + chunk)*CC + c] = cs;
    }
}

// ---------------- mid: inter-chunk carry scans ----------------
__global__ void k_mid() {
    int g = blockIdx.x * blockDim.x + threadIdx.x;   // BB*CC*NN = 8192
    int b = g / (CC*NN);
    int cn = g % (CC*NN);
    int c = cn / NN;
    float Acn = ((const float*)g_A4)[cn];
    const float* gef = (const float*)g_ef4;
    const float* geb = (const float*)g_eb4;
    const float* gec = (const float*)g_ec4;
    float* gc1 = (float*)g_c14;
    float* gc2 = (float*)g_c24;
    float* gc3 = (float*)g_c34;
    float* gc4 = (float*)g_c44;
    size_t ebase = (size_t)b*RR*CC*NN + cn;
    int rbase = b*RR*CC + c;

    float cur = 0.f;
    for (int r = 0; r < RR; r++) {
        size_t ei = ebase + (size_t)r*CC*NN;
        gc1[ei] = cur;
        float G = __expf(Acn * g_rs[rbase + r*CC]);
        cur = fmaf(G, cur, gef[ei]);
    }
    float cur2 = 0.f, cur3 = 0.f;
    for (int r = RR-1; r >= 0; r--) {
        size_t ei = ebase + (size_t)r*CC*NN;
        gc2[ei] = cur2;
        gc3[ei] = cur3;
        float G = __expf(Acn * g_rs[rbase + r*CC]);
        cur2 = fmaf(G, cur2, geb[ei]);
        cur3 = fmaf(G, cur3, gef[ei]);
    }
    float cur4 = 0.f;
    for (int w = RR-1; w >= 0; w--) {
        size_t ei = ebase + (size_t)w*CC*NN;
        gc4[ei] = cur4;
        float G = __expf(Acn * g_cs[rbase + w*CC]);
        cur4 = fmaf(G, cur4, gec[ei]);
    }
}

// ---------------- pass2: local scans with carries, emit y ----------------
__global__ void __launch_bounds__(256, 3) k_pass2() {
    int blk = blockIdx.x;
    bool isCol = blk >= BB*RR*2;
    int bid = isCol ? blk - BB*RR*2 : blk;
    int b = bid / (RR*2);
    int rem = bid % (RR*2);
    int chunk = rem >> 1;
    int cg = rem & 1;
    int half = threadIdx.x & 1;
    int c = cg*128 + (threadIdx.x >> 1);

    float Acn[NH];
    {
        float4 a0 = g_A4[c*4 + half*2];
        float4 a1 = g_A4[c*4 + half*2 + 1];
        Acn[0]=a0.x; Acn[1]=a0.y; Acn[2]=a0.z; Acn[3]=a0.w;
        Acn[4]=a1.x; Acn[5]=a1.y; Acn[6]=a1.z; Acn[7]=a1.w;
    }
    int i4 = ((b*RR + chunk)*CC + c)*4 + half*2;

    if (!isCol) {
        float h1[NH], h3[NH];
        {
            float4 v0 = g_c14[i4], v1 = g_c14[i4+1];
            h1[0]=v0.x; h1[1]=v0.y; h1[2]=v0.z; h1[3]=v0.w;
            h1[4]=v1.x; h1[5]=v1.y; h1[6]=v1.z; h1[7]=v1.w;
            float4 w0 = g_c34[i4], w1 = g_c34[i4+1];
            h3[0]=w0.x; h3[1]=w0.y; h3[2]=w0.z; h3[3]=w0.w;
            h3[4]=w1.x; h3[5]=w1.y; h3[6]=w1.z; h3[7]=w1.w;
        }
        // ascending: dir1 + dir3
        #pragma unroll 2
        for (int ts = 0; ts < 64; ts++) {
            int p = chunk*64 + ts;
            size_t idx = ((size_t)(b*LL + p))*CC + c;
            float2 du = g_du[idx];
            float d = du.x, uu = du.y;
            float bm[NH], cm[NH];
            {
                float4 v0 = g_Bm4[(b*LL + p)*4 + half*2];
                float4 v1 = g_Bm4[(b*LL + p)*4 + half*2 + 1];
                bm[0]=v0.x; bm[1]=v0.y; bm[2]=v0.z; bm[3]=v0.w;
                bm[4]=v1.x; bm[5]=v1.y; bm[6]=v1.z; bm[7]=v1.w;
                float4 u0 = g_Cm4[(b*LL + p)*4 + half*2];
                float4 u1 = g_Cm4[(b*LL + p)*4 + half*2 + 1];
                cm[0]=u0.x; cm[1]=u0.y; cm[2]=u0.z; cm[3]=u0.w;
                cm[4]=u1.x; cm[5]=u1.y; cm[6]=u1.z; cm[7]=u1.w;
            }
            float y = 0.f;
            #pragma unroll
            for (int n = 0; n < NH; n++) {
                float a = __expf(d * Acn[n]);
                float w = uu * bm[n];
                h1[n] = fmaf(a, h1[n], w);
                h3[n] = fmaf(a, h3[n], w);
                y = fmaf(h1[n] + h3[n], cm[n], y);
            }
            float ytot = y + __shfl_xor_sync(0xffffffffu, y, 1);
            if (half == 0) g_y13[idx] = ytot;
        }
        // descending: dir2, accumulate into g_y13
        float h2[NH];
        {
            float4 v0 = g_c24[i4], v1 = g_c24[i4+1];
            h2[0]=v0.x; h2[1]=v0.y; h2[2]=v0.z; h2[3]=v0.w;
            h2[4]=v1.x; h2[5]=v1.y; h2[6]=v1.z; h2[7]=v1.w;
        }
        #pragma unroll 2
        for (int ts = 63; ts >= 0; ts--) {
            int p = chunk*64 + ts;
            size_t idx = ((size_t)(b*LL + p))*CC + c;
            float2 du = g_du[idx];
            float d = du.x, uu = du.y;
            float bm[NH], cm[NH];
            {
                float4 v0 = g_Bm4[(b*LL + p)*4 + half*2];
                float4 v1 = g_Bm4[(b*LL + p)*4 + half*2 + 1];
                bm[0]=v0.x; bm[1]=v0.y; bm[2]=v0.z; bm[3]=v0.w;
                bm[4]=v1.x; bm[5]=v1.y; bm[6]=v1.z; bm[7]=v1.w;
                float4 u0 = g_Cm4[(b*LL + p)*4 + half*2];
                float4 u1 = g_Cm4[(b*LL + p)*4 + half*2 + 1];
                cm[0]=u0.x; cm[1]=u0.y; cm[2]=u0.z; cm[3]=u0.w;
                cm[4]=u1.x; cm[5]=u1.y; cm[6]=u1.z; cm[7]=u1.w;
            }
            float y = 0.f;
            #pragma unroll
            for (int n = 0; n < NH; n++) {
                float a = __expf(d * Acn[n]);
                float w = uu * bm[n];
                h2[n] = fmaf(a, h2[n], w);
                y = fmaf(h2[n], cm[n], y);
            }
            float ytot = y + __shfl_xor_sync(0xffffffffu, y, 1);
            if (half == 0) g_y13[idx] += ytot;
        }
    } else {
        float h4[NH];
        {
            float4 v0 = g_c44[i4], v1 = g_c44[i4+1];
            h4[0]=v0.x; h4[1]=v0.y; h4[2]=v0.z; h4[3]=v0.w;
            h4[4]=v1.x; h4[5]=v1.y; h4[6]=v1.z; h4[7]=v1.w;
        }
        #pragma unroll 2
        for (int h = 0; h < 64; h++) {
            int p = h*64 + chunk;
            size_t idx = ((size_t)(b*LL + p))*CC + c;
            float2 du = g_du[idx];
            float d = du.x, uu = du.y;
            float bm[NH], cm[NH];
            {
                float4 v0 = g_Bm4[(b*LL + p)*4 + half*2];
                float4 v1 = g_Bm4[(b*LL + p)*4 + half*2 + 1];
                bm[0]=v0.x; bm[1]=v0.y; bm[2]=v0.z; bm[3]=v0.w;
                bm[4]=v1.x; bm[5]=v1.y; bm[6]=v1.z; bm[7]=v1.w;
                float4 u0 = g_Cm4[(b*LL + p)*4 + half*2];
                float4 u1 = g_Cm4[(b*LL + p)*4 + half*2 + 1];
                cm[0]=u0.x; cm[1]=u0.y; cm[2]=u0.z; cm[3]=u0.w;
                cm[4]=u1.x; cm[5]=u1.y; cm[6]=u1.z; cm[7]=u1.w;
            }
            float y = 0.f;
            #pragma unroll
            for (int n = 0; n < NH; n++) {
                float a = __expf(d * Acn[n]);
                float wv = uu * bm[n];
                h4[n] = fmaf(a, h4[n], wv);
                y = fmaf(h4[n], cm[n], y);
            }
            float ytot = y + __shfl_xor_sync(0xffffffffu, y, 1);
            if (half == 0) g_y4[idx] = ytot;
        }
    }
}

// ---------------- final: combine, add x*D, transpose (p,c) -> (c,p) ----------------
__global__ void k_final(const float* __restrict__ F,
                        const float* __restrict__ Dv,
                        float* __restrict__ out)
{
    __shared__ float tile[32][33];
    int p0 = blockIdx.x * 32;
    int c0 = blockIdx.y * 32;
    int b = blockIdx.z;
    int tx = threadIdx.x, ty = threadIdx.y;   // (32, 8)
    #pragma unroll
    for (int i = 0; i < 4; i++) {
        int p = p0 + ty + i*8;
        size_t idx = ((size_t)(b*LL + p))*CC + c0 + tx;
        tile[ty + i*8][tx] = g_y13[idx] + g_y4[idx];
    }
    __syncthreads();
    #pragma unroll
    for (int i = 0; i < 4; i++) {
        int cc = c0 + ty + i*8;
        int p = p0 + tx;
        size_t o = (size_t)b*CC*LL + (size_t)cc*LL + p;
        out[o] = 0.25f * tile[tx][ty + i*8] + F[o] * Dv[cc];
    }
}

// ---------------- launch ----------------
extern "C" void kernel_launch(void* const* d_in, const int* in_sizes, int n_in,
                              void* d_out, int out_size) {
    const float* F     = (const float*)d_in[0];
    const float* A_log = (const float*)d_in[1];
    const float* Dv    = (const float*)d_in[2];
    const float* Wd    = (const float*)d_in[3];
    const float* bd    = (const float*)d_in[4];
    const float* WB    = (const float*)d_in[5];
    const float* WC    = (const float*)d_in[6];
    float* out = (float*)d_out;

    k_prep<<<16, 256>>>(A_log);
    k_gemm_bc<<<BB*LL/64, 256>>>(F, WB, WC);
    {
        dim3 gd(BB*LL/64, CC/64);
        k_gemm_delta<<<gd, 256>>>(F, Wd, bd);
    }
    k_pass1<<<2*BB*RR*2, 256>>>();
    k_mid<<<BB*CC*NN/256, 256>>>();
    k_pass2<<<2*BB*RR*2, 256>>>();
    k_final<<<dim3(LL/32, CC/32, BB), dim3(32, 8)>>>(F, Dv, out);
}

// round 4
// speedup vs baseline: 1.1914x; 1.0991x over previous
#include <cuda_runtime.h>
#include <cuda_bf16.h>

#define BB 2
#define CC 256
#define LL 4096
#define NN 16
#define RR 64
#define NH 4    // n-values per thread (n split across lane quads)

// ---------------- static device scratch (no allocations) ----------------
__device__ float4 g_A4   [CC*NN/4];          // A2 = -exp(A_log)*log2(e), (c,n)
__device__ float2 g_du   [BB*LL*CC];         // (delta, delta*x) packed
__device__ float4 g_Bm4  [BB*LL*NN/4];       // (b,p,n)
__device__ float4 g_Cm4  [BB*LL*NN/4];
__device__ float  g_rs   [BB*RR*CC];         // row delta sums
__device__ float  g_cs   [BB*RR*CC];         // col delta sums
__device__ float4 g_ef4  [BB*RR*CC*NN/4];    // row fwd local end states
__device__ float4 g_eb4  [BB*RR*CC*NN/4];    // row bwd local end states
__device__ float4 g_ec4  [BB*RR*CC*NN/4];    // col fwd local end states
__device__ float4 g_c14  [BB*RR*CC*NN/4];    // carries per chunk, dir 1..4
__device__ float4 g_c24  [BB*RR*CC*NN/4];
__device__ float4 g_c34  [BB*RR*CC*NN/4];
__device__ float4 g_c44  [BB*RR*CC*NN/4];
__device__ float  g_y13  [BB*LL*CC];         // y1+y2+y3
__device__ float  g_y4   [BB*LL*CC];

__device__ __forceinline__ float ex2f(float x) {
    float r; asm("ex2.approx.f32 %0, %1;" : "=f"(r) : "f"(x)); return r;
}

// ---------------- prep: A2 = -exp(A_log) * log2(e) ----------------
__global__ void k_prep(const float* __restrict__ A_log) {
    int i = blockIdx.x * blockDim.x + threadIdx.x;
    if (i < CC*NN) ((float*)g_A4)[i] = -expf(A_log[i]) * 1.4426950408889634f;
}

// ---------------- small GEMM: Bm = x@W_B, Cm = x@W_C ----------------
__global__ void __launch_bounds__(256) k_gemm_bc(
    const float* __restrict__ F,
    const float* __restrict__ W_B,
    const float* __restrict__ W_C)
{
    __shared__ float Ws[64][32];
    __shared__ float xs[64][64];
    int t = threadIdx.x;
    int m0 = blockIdx.x * 64;
    int b = m0 / LL;
    int pbase = m0 % LL;
    int n = t & 31;
    int tw = t >> 5;
    float acc[8] = {0,0,0,0,0,0,0,0};

    for (int kc = 0; kc < 4; kc++) {
        int k0 = kc * 64;
        __syncthreads();
        #pragma unroll
        for (int i = 0; i < 8; i++) {
            int e = t + i*256;
            int kk = e >> 5, nn = e & 31;
            int k = k0 + kk;
            Ws[kk][nn] = (nn < 16) ? W_B[k*16 + nn] : W_C[k*16 + (nn-16)];
        }
        #pragma unroll
        for (int i = 0; i < 16; i++) {
            int e = t + i*256;
            int m = e & 63, kk = e >> 6;
            xs[kk][m] = F[(size_t)b*CC*LL + (size_t)(k0+kk)*LL + pbase + m];
        }
        __syncthreads();
        for (int kk = 0; kk < 64; kk++) {
            float w = Ws[kk][n];
            #pragma unroll
            for (int mi = 0; mi < 8; mi++)
                acc[mi] = fmaf(xs[kk][tw + mi*8], w, acc[mi]);
        }
    }
    float* gBm = (float*)g_Bm4;
    float* gCm = (float*)g_Cm4;
    #pragma unroll
    for (int mi = 0; mi < 8; mi++) {
        int m = m0 + tw + mi*8;
        if (n < 16) gBm[m*NN + n] = acc[mi];
        else        gCm[m*NN + (n-16)] = acc[mi];
    }
}

// ---------------- big GEMM: xw = x@W_delta + b_delta -> (delta, delta*x) ----------------
__global__ void __launch_bounds__(256) k_gemm_delta(
    const float* __restrict__ F,
    const float* __restrict__ Wd,
    const float* __restrict__ bd)
{
    __shared__ float As[32][64];
    __shared__ float Bs[32][64];
    int t = threadIdx.x;
    int m0 = blockIdx.x * 64;
    int n0 = blockIdx.y * 64;
    int b = m0 / LL;
    int pbase = m0 % LL;
    int tm0 = (t & 15) * 4;
    int tn0 = (t >> 4) * 4;
    float acc[4][4] = {};

    for (int kc = 0; kc < 8; kc++) {
        int k0 = kc * 32;
        __syncthreads();
        #pragma unroll
        for (int i = 0; i < 8; i++) {
            int e = t + i*256;
            int m = e & 63, k = e >> 6;
            As[k][m] = F[(size_t)b*CC*LL + (size_t)(k0+k)*LL + pbase + m];
            Bs[k][m] = Wd[(k0+k)*CC + n0 + m];
        }
        __syncthreads();
        #pragma unroll
        for (int k = 0; k < 32; k++) {
            float4 a4 = *(const float4*)&As[k][tm0];
            float4 b4 = *(const float4*)&Bs[k][tn0];
            float av[4] = {a4.x, a4.y, a4.z, a4.w};
            float bv[4] = {b4.x, b4.y, b4.z, b4.w};
            #pragma unroll
            for (int i = 0; i < 4; i++)
                #pragma unroll
                for (int j = 0; j < 4; j++)
                    acc[i][j] = fmaf(av[i], bv[j], acc[i][j]);
        }
    }
    #pragma unroll
    for (int i = 0; i < 4; i++) {
        int p = pbase + tm0 + i;
        size_t mg = (size_t)(m0 + tm0 + i);
        #pragma unroll
        for (int j = 0; j < 4; j++) {
            int c = n0 + tn0 + j;
            float xw = acc[i][j] + bd[c];
            float sp = (xw > 0.f) ? xw + log1pf(__expf(-xw)) : log1pf(__expf(xw));
            float xv = F[(size_t)b*CC*LL + (size_t)c*LL + p];
            g_du[mg*CC + c] = make_float2(sp, sp * xv);
        }
    }
}

// ---------------- pass1: per-chunk local end states + delta sums ----------------
// grid = 1024 blocks: [0,512) rows, [512,1024) cols.
// block = 64 channels x 4 n-quads; q = tid&3, c = cg*64 + (tid>>2).
__global__ void __launch_bounds__(256) k_pass1() {
    int blk = blockIdx.x;
    bool isCol = blk >= BB*RR*4;
    int bid = isCol ? blk - BB*RR*4 : blk;
    int b = bid / (RR*4);
    int rem = bid % (RR*4);
    int chunk = rem >> 2;
    int cg = rem & 3;
    int q = threadIdx.x & 3;
    int c = cg*64 + (threadIdx.x >> 2);

    float A2[NH];
    {
        float4 a0 = g_A4[c*4 + q];
        A2[0]=a0.x; A2[1]=a0.y; A2[2]=a0.z; A2[3]=a0.w;
    }

    if (!isCol) {
        float ef[NH], eb[NH], Pp[NH];
        #pragma unroll
        for (int n = 0; n < NH; n++) { ef[n]=0.f; eb[n]=0.f; Pp[n]=1.f; }
        float rs = 0.f;
        #pragma unroll 4
        for (int ts = 0; ts < 64; ts++) {
            int p = chunk*64 + ts;
            size_t idx = ((size_t)(b*LL + p))*CC + c;
            float2 du = g_du[idx];
            float d = du.x, uu = du.y;
            rs += d;
            float4 v = g_Bm4[(b*LL + p)*4 + q];
            float bm[NH] = {v.x, v.y, v.z, v.w};
            #pragma unroll
            for (int n = 0; n < NH; n++) {
                float a = ex2f(d * A2[n]);
                float w = uu * bm[n];
                eb[n] = fmaf(w, Pp[n], eb[n]);
                Pp[n] *= a;
                ef[n] = fmaf(a, ef[n], w);
            }
        }
        int i4 = ((b*RR + chunk)*CC + c)*4 + q;
        g_ef4[i4] = make_float4(ef[0],ef[1],ef[2],ef[3]);
        g_eb4[i4] = make_float4(eb[0],eb[1],eb[2],eb[3]);
        if (q == 0) g_rs[(b*RR + chunk)*CC + c] = rs;
    } else {
        float ec[NH];
        #pragma unroll
        for (int n = 0; n < NH; n++) ec[n] = 0.f;
        float cs = 0.f;
        #pragma unroll 4
        for (int h = 0; h < 64; h++) {
            int p = h*64 + chunk;
            size_t idx = ((size_t)(b*LL + p))*CC + c;
            float2 du = g_du[idx];
            float d = du.x, uu = du.y;
            cs += d;
            float4 v = g_Bm4[(b*LL + p)*4 + q];
            float bm[NH] = {v.x, v.y, v.z, v.w};
            #pragma unroll
            for (int n = 0; n < NH; n++) {
                float a = ex2f(d * A2[n]);
                float wv = uu * bm[n];
                ec[n] = fmaf(a, ec[n], wv);
            }
        }
        int i4 = ((b*RR + chunk)*CC + c)*4 + q;
        g_ec4[i4] = make_float4(ec[0],ec[1],ec[2],ec[3]);
        if (q == 0) g_cs[(b*RR + chunk)*CC + c] = cs;
    }
}

// ---------------- mid: inter-chunk carry scans, 3-way parallel ----------------
__global__ void k_mid() {
    int g = blockIdx.x * blockDim.x + threadIdx.x;   // BB*CC*NN = 8192
    int which = blockIdx.y;                           // 0: dir1, 1: dir2+3, 2: dir4
    int b = g / (CC*NN);
    int cn = g % (CC*NN);
    int c = cn / NN;
    float A2 = ((const float*)g_A4)[cn];
    const float* gef = (const float*)g_ef4;
    const float* geb = (const float*)g_eb4;
    const float* gec = (const float*)g_ec4;
    float* gc1 = (float*)g_c14;
    float* gc2 = (float*)g_c24;
    float* gc3 = (float*)g_c34;
    float* gc4 = (float*)g_c44;
    size_t ebase = (size_t)b*RR*CC*NN + cn;
    int rbase = b*RR*CC + c;

    if (which == 0) {
        float cur = 0.f;
        for (int r = 0; r < RR; r++) {
            size_t ei = ebase + (size_t)r*CC*NN;
            gc1[ei] = cur;
            float G = ex2f(A2 * g_rs[rbase + r*CC]);
            cur = fmaf(G, cur, gef[ei]);
        }
    } else if (which == 1) {
        float cur2 = 0.f, cur3 = 0.f;
        for (int r = RR-1; r >= 0; r--) {
            size_t ei = ebase + (size_t)r*CC*NN;
            gc2[ei] = cur2;
            gc3[ei] = cur3;
            float G = ex2f(A2 * g_rs[rbase + r*CC]);
            cur2 = fmaf(G, cur2, geb[ei]);
            cur3 = fmaf(G, cur3, gef[ei]);
        }
    } else {
        float cur4 = 0.f;
        for (int w = RR-1; w >= 0; w--) {
            size_t ei = ebase + (size_t)w*CC*NN;
            gc4[ei] = cur4;
            float G = ex2f(A2 * g_cs[rbase + w*CC]);
            cur4 = fmaf(G, cur4, gec[ei]);
        }
    }
}

// ---------------- pass2: local scans with carries, emit y ----------------
__global__ void __launch_bounds__(256) k_pass2() {
    int blk = blockIdx.x;
    bool isCol = blk >= BB*RR*4;
    int bid = isCol ? blk - BB*RR*4 : blk;
    int b = bid / (RR*4);
    int rem = bid % (RR*4);
    int chunk = rem >> 2;
    int cg = rem & 3;
    int q = threadIdx.x & 3;
    int c = cg*64 + (threadIdx.x >> 2);

    float A2[NH];
    {
        float4 a0 = g_A4[c*4 + q];
        A2[0]=a0.x; A2[1]=a0.y; A2[2]=a0.z; A2[3]=a0.w;
    }
    int i4 = ((b*RR + chunk)*CC + c)*4 + q;

    if (!isCol) {
        float h1[NH], h3[NH];
        {
            float4 v0 = g_c14[i4];
            h1[0]=v0.x; h1[1]=v0.y; h1[2]=v0.z; h1[3]=v0.w;
            float4 w0 = g_c34[i4];
            h3[0]=w0.x; h3[1]=w0.y; h3[2]=w0.z; h3[3]=w0.w;
        }
        // ascending: dir1 + dir3
        #pragma unroll 4
        for (int ts = 0; ts < 64; ts++) {
            int p = chunk*64 + ts;
            size_t idx = ((size_t)(b*LL + p))*CC + c;
            float2 du = g_du[idx];
            float d = du.x, uu = du.y;
            float4 v = g_Bm4[(b*LL + p)*4 + q];
            float bm[NH] = {v.x, v.y, v.z, v.w};
            float4 u = g_Cm4[(b*LL + p)*4 + q];
            float cm[NH] = {u.x, u.y, u.z, u.w};
            float y = 0.f;
            #pragma unroll
            for (int n = 0; n < NH; n++) {
                float a = ex2f(d * A2[n]);
                float w = uu * bm[n];
                h1[n] = fmaf(a, h1[n], w);
                h3[n] = fmaf(a, h3[n], w);
                y = fmaf(h1[n] + h3[n], cm[n], y);
            }
            y += __shfl_xor_sync(0xffffffffu, y, 1);
            y += __shfl_xor_sync(0xffffffffu, y, 2);
            if (q == 0) g_y13[idx] = y;
        }
        // descending: dir2, accumulate into g_y13
        float h2[NH];
        {
            float4 v0 = g_c24[i4];
            h2[0]=v0.x; h2[1]=v0.y; h2[2]=v0.z; h2[3]=v0.w;
        }
        #pragma unroll 4
        for (int ts = 63; ts >= 0; ts--) {
            int p = chunk*64 + ts;
            size_t idx = ((size_t)(b*LL + p))*CC + c;
            float2 du = g_du[idx];
            float d = du.x, uu = du.y;
            float4 v = g_Bm4[(b*LL + p)*4 + q];
            float bm[NH] = {v.x, v.y, v.z, v.w};
            float4 u = g_Cm4[(b*LL + p)*4 + q];
            float cm[NH] = {u.x, u.y, u.z, u.w};
            float y = 0.f;
            #pragma unroll
            for (int n = 0; n < NH; n++) {
                float a = ex2f(d * A2[n]);
                float w = uu * bm[n];
                h2[n] = fmaf(a, h2[n], w);
                y = fmaf(h2[n], cm[n], y);
            }
            y += __shfl_xor_sync(0xffffffffu, y, 1);
            y += __shfl_xor_sync(0xffffffffu, y, 2);
            if (q == 0) g_y13[idx] += y;
        }
    } else {
        float h4[NH];
        {
            float4 v0 = g_c44[i4];
            h4[0]=v0.x; h4[1]=v0.y; h4[2]=v0.z; h4[3]=v0.w;
        }
        #pragma unroll 4
        for (int h = 0; h < 64; h++) {
            int p = h*64 + chunk;
            size_t idx = ((size_t)(b*LL + p))*CC + c;
            float2 du = g_du[idx];
            float d = du.x, uu = du.y;
            float4 v = g_Bm4[(b*LL + p)*4 + q];
            float bm[NH] = {v.x, v.y, v.z, v.w};
            float4 u = g_Cm4[(b*LL + p)*4 + q];
            float cm[NH] = {u.x, u.y, u.z, u.w};
            float y = 0.f;
            #pragma unroll
            for (int n = 0; n < NH; n++) {
                float a = ex2f(d * A2[n]);
                float wv = uu * bm[n];
                h4[n] = fmaf(a, h4[n], wv);
                y = fmaf(h4[n], cm[n], y);
            }
            y += __shfl_xor_sync(0xffffffffu, y, 1);
            y += __shfl_xor_sync(0xffffffffu, y, 2);
            if (q == 0) g_y4[idx] = y;
        }
    }
}

// ---------------- final: combine, add x*D, transpose (p,c) -> (c,p) ----------------
__global__ void k_final(const float* __restrict__ F,
                        const float* __restrict__ Dv,
                        float* __restrict__ out)
{
    __shared__ float tile[32][33];
    int p0 = blockIdx.x * 32;
    int c0 = blockIdx.y * 32;
    int b = blockIdx.z;
    int tx = threadIdx.x, ty = threadIdx.y;   // (32, 8)
    #pragma unroll
    for (int i = 0; i < 4; i++) {
        int p = p0 + ty + i*8;
        size_t idx = ((size_t)(b*LL + p))*CC + c0 + tx;
        tile[ty + i*8][tx] = g_y13[idx] + g_y4[idx];
    }
    __syncthreads();
    #pragma unroll
    for (int i = 0; i < 4; i++) {
        int cc = c0 + ty + i*8;
        int p = p0 + tx;
        size_t o = (size_t)b*CC*LL + (size_t)cc*LL + p;
        out[o] = 0.25f * tile[tx][ty + i*8] + F[o] * Dv[cc];
    }
}

// ---------------- launch ----------------
extern "C" void kernel_launch(void* const* d_in, const int* in_sizes, int n_in,
                              void* d_out, int out_size) {
    const float* F     = (const float*)d_in[0];
    const float* A_log = (const float*)d_in[1];
    const float* Dv    = (const float*)d_in[2];
    const float* Wd    = (const float*)d_in[3];
    const float* bd    = (const float*)d_in[4];
    const float* WB    = (const float*)d_in[5];
    const float* WC    = (const float*)d_in[6];
    float* out = (float*)d_out;

    k_prep<<<16, 256>>>(A_log);
    k_gemm_bc<<<BB*LL/64, 256>>>(F, WB, WC);
    {
        dim3 gd(BB*LL/64, CC/64);
        k_gemm_delta<<<gd, 256>>>(F, Wd, bd);
    }
    k_pass1<<<2*BB*RR*4, 256>>>();
    k_mid<<<dim3(BB*CC*NN/256, 3), 256>>>();
    k_pass2<<<2*BB*RR*4, 256>>>();
    k_final<<<dim3(LL/32, CC/32, BB), dim3(32, 8)>>>(F, Dv, out);
}

// round 5
// speedup vs baseline: 1.3041x; 1.0946x over previous
#include <cuda_runtime.h>
#include <cuda_bf16.h>

#define BB 2
#define CC 256
#define LL 4096
#define NN 16
#define RR 64
#define NH 4    // n-values per thread (n split across lane quads)

// ---------------- static device scratch (no allocations) ----------------
__device__ float4 g_A4   [CC*NN/4];          // A2 = -exp(A_log)*log2(e), (c,n)
__device__ float2 g_du   [BB*LL*CC];         // (delta, delta*x) packed
__device__ float4 g_Bm4  [BB*LL*NN/4];       // (b,p,n)
__device__ float4 g_Cm4  [BB*LL*NN/4];
__device__ float  g_rs   [BB*RR*CC];         // row delta sums
__device__ float  g_cs   [BB*RR*CC];         // col delta sums
__device__ float4 g_ef4  [BB*RR*CC*NN/4];    // row fwd local end states
__device__ float4 g_eb4  [BB*RR*CC*NN/4];    // row bwd local end states
__device__ float4 g_ec4  [BB*RR*CC*NN/4];    // col fwd local end states
__device__ float4 g_c14  [BB*RR*CC*NN/4];    // carries per chunk, dir 1..4
__device__ float4 g_c24  [BB*RR*CC*NN/4];
__device__ float4 g_c34  [BB*RR*CC*NN/4];
__device__ float4 g_c44  [BB*RR*CC*NN/4];
__device__ float  g_y13  [BB*LL*CC];         // y1+y2+y3
__device__ float  g_y4   [BB*LL*CC];

__device__ __forceinline__ float ex2f(float x) {
    float r; asm("ex2.approx.f32 %0, %1;" : "=f"(r) : "f"(x)); return r;
}

__device__ __forceinline__ void split_tf32(float x, unsigned& hi, unsigned& lo) {
    unsigned h; asm("cvt.rna.tf32.f32 %0, %1;" : "=r"(h) : "f"(x));
    float hf = __uint_as_float(h);
    float l = x - hf;
    unsigned lw; asm("cvt.rna.tf32.f32 %0, %1;" : "=r"(lw) : "f"(l));
    hi = h; lo = lw;
}

#define MMA8(acc, a, bq) asm volatile( \
  "mma.sync.aligned.m16n8k8.row.col.f32.tf32.tf32.f32 " \
  "{%0,%1,%2,%3},{%4,%5,%6,%7},{%8,%9},{%0,%1,%2,%3};\n" \
  : "+f"(acc[0]),"+f"(acc[1]),"+f"(acc[2]),"+f"(acc[3]) \
  : "r"(a[0]),"r"(a[1]),"r"(a[2]),"r"(a[3]), "r"(bq[0]),"r"(bq[1]))

__device__ __forceinline__ float softplusf(float xw) {
    return (xw > 0.f) ? xw + log1pf(__expf(-xw)) : log1pf(__expf(xw));
}

// ---------------- small GEMM: Bm = x@W_B, Cm = x@W_C (+ fused A prep) ----------------
__global__ void __launch_bounds__(256) k_gemm_bc(
    const float* __restrict__ F,
    const float* __restrict__ W_B,
    const float* __restrict__ W_C,
    const float* __restrict__ A_log)
{
    // fused prep: A2 = -exp(A_log) * log2(e)
    if (blockIdx.x < 16) {
        int i = blockIdx.x * 256 + threadIdx.x;
        ((float*)g_A4)[i] = -expf(A_log[i]) * 1.4426950408889634f;
    }
    __shared__ float Ws[64][32];
    __shared__ float xs[64][64];
    int t = threadIdx.x;
    int m0 = blockIdx.x * 64;
    int b = m0 / LL;
    int pbase = m0 % LL;
    int n = t & 31;
    int tw = t >> 5;
    float acc[8] = {0,0,0,0,0,0,0,0};

    for (int kc = 0; kc < 4; kc++) {
        int k0 = kc * 64;
        __syncthreads();
        #pragma unroll
        for (int i = 0; i < 8; i++) {
            int e = t + i*256;
            int kk = e >> 5, nn = e & 31;
            int k = k0 + kk;
            Ws[kk][nn] = (nn < 16) ? W_B[k*16 + nn] : W_C[k*16 + (nn-16)];
        }
        #pragma unroll
        for (int i = 0; i < 16; i++) {
            int e = t + i*256;
            int m = e & 63, kk = e >> 6;
            xs[kk][m] = F[(size_t)b*CC*LL + (size_t)(k0+kk)*LL + pbase + m];
        }
        __syncthreads();
        for (int kk = 0; kk < 64; kk++) {
            float w = Ws[kk][n];
            #pragma unroll
            for (int mi = 0; mi < 8; mi++)
                acc[mi] = fmaf(xs[kk][tw + mi*8], w, acc[mi]);
        }
    }
    float* gBm = (float*)g_Bm4;
    float* gCm = (float*)g_Cm4;
    #pragma unroll
    for (int mi = 0; mi < 8; mi++) {
        int m = m0 + tw + mi*8;
        if (n < 16) gBm[m*NN + n] = acc[mi];
        else        gCm[m*NN + (n-16)] = acc[mi];
    }
}

// ---------------- big GEMM (tensor cores, tf32 compensated) ----------------
// BM=128, BN=64, BK=16, 8 warps (4m x 2n), warp tile 32x32.
__global__ void __launch_bounds__(256) k_gemm_delta_tc(
    const float* __restrict__ F,
    const float* __restrict__ Wd,
    const float* __restrict__ bd)
{
    __shared__ float As[2][16][132];
    __shared__ float Bs[2][16][68];
    int t = threadIdx.x;
    int m0 = blockIdx.x * 128;
    int n0 = blockIdx.y * 64;
    int b = m0 / LL;
    int pbase = m0 % LL;
    int warp = t >> 5, lane = t & 31;
    int wm = warp >> 1, wn = warp & 1;
    int lr = lane >> 2, lc = lane & 3;

    const float* Fb = F + (size_t)b*CC*LL + pbase;
    float acc[2][4][4] = {};

    // stage chunk into buf via cp.async
    auto stage = [&](int chunk, int buf) {
        int k0 = chunk * 16;
        #pragma unroll
        for (int i = 0; i < 2; i++) {          // As: 512 float4 slots
            int s = t + i*256;
            int k = s >> 5, m4 = (s & 31) << 2;
            unsigned dst = (unsigned)__cvta_generic_to_shared(&As[buf][k][m4]);
            const float* src = Fb + (size_t)(k0+k)*LL + m4;
            asm volatile("cp.async.cg.shared.global [%0], [%1], 16;\n" :: "r"(dst), "l"(src));
        }
        {                                       // Bs: 256 float4 slots
            int s = t;
            int k = s >> 4, n4 = (s & 15) << 2;
            unsigned dst = (unsigned)__cvta_generic_to_shared(&Bs[buf][k][n4]);
            const float* src = Wd + (size_t)(k0+k)*CC + n0 + n4;
            asm volatile("cp.async.cg.shared.global [%0], [%1], 16;\n" :: "r"(dst), "l"(src));
        }
        asm volatile("cp.async.commit_group;\n");
    };

    stage(0, 0);
    for (int chunk = 0; chunk < 16; chunk++) {
        int buf = chunk & 1;
        if (chunk < 15) {
            stage(chunk+1, buf^1);
            asm volatile("cp.async.wait_group 1;\n");
        } else {
            asm volatile("cp.async.wait_group 0;\n");
        }
        __syncthreads();
        #pragma unroll
        for (int kk = 0; kk < 16; kk += 8) {
            unsigned ah[2][4], al[2][4], bh[4][2], bl[4][2];
            #pragma unroll
            for (int mt = 0; mt < 2; mt++) {
                int row = wm*32 + mt*16 + lr;
                split_tf32(As[buf][kk+lc][row],     ah[mt][0], al[mt][0]);
                split_tf32(As[buf][kk+lc][row+8],   ah[mt][1], al[mt][1]);
                split_tf32(As[buf][kk+4+lc][row],   ah[mt][2], al[mt][2]);
                split_tf32(As[buf][kk+4+lc][row+8], ah[mt][3], al[mt][3]);
            }
            #pragma unroll
            for (int nt = 0; nt < 4; nt++) {
                int n = wn*32 + nt*8 + lr;
                split_tf32(Bs[buf][kk+lc][n],   bh[nt][0], bl[nt][0]);
                split_tf32(Bs[buf][kk+4+lc][n], bh[nt][1], bl[nt][1]);
            }
            #pragma unroll
            for (int mt = 0; mt < 2; mt++)
                #pragma unroll
                for (int nt = 0; nt < 4; nt++) {
                    MMA8(acc[mt][nt], ah[mt], bh[nt]);
                    MMA8(acc[mt][nt], ah[mt], bl[nt]);
                    MMA8(acc[mt][nt], al[mt], bh[nt]);
                }
        }
        __syncthreads();
    }

    // epilogue: bias + softplus + pack (delta, delta*x)
    #pragma unroll
    for (int mt = 0; mt < 2; mt++) {
        int m_lo = wm*32 + mt*16 + lr;
        #pragma unroll
        for (int nt = 0; nt < 4; nt++) {
            int n = n0 + wn*32 + nt*8 + lc*2;
            float b0 = bd[n], b1 = bd[n+1];
            #pragma unroll
            for (int h = 0; h < 2; h++) {
                int m = m_lo + h*8;
                size_t mg = (size_t)m0 + m;
                float sp0 = softplusf(acc[mt][nt][h*2+0] + b0);
                float sp1 = softplusf(acc[mt][nt][h*2+1] + b1);
                float x0 = Fb[(size_t)n*LL + m];
                float x1 = Fb[(size_t)(n+1)*LL + m];
                g_du[mg*CC + n]     = make_float2(sp0, sp0*x0);
                g_du[mg*CC + n + 1] = make_float2(sp1, sp1*x1);
            }
        }
    }
}

// ---------------- pass1: per-chunk local end states + delta sums ----------------
__global__ void __launch_bounds__(256) k_pass1() {
    int blk = blockIdx.x;
    bool isCol = blk >= BB*RR*4;
    int bid = isCol ? blk - BB*RR*4 : blk;
    int b = bid / (RR*4);
    int rem = bid % (RR*4);
    int chunk = rem >> 2;
    int cg = rem & 3;
    int q = threadIdx.x & 3;
    int c = cg*64 + (threadIdx.x >> 2);

    float A2[NH];
    {
        float4 a0 = g_A4[c*4 + q];
        A2[0]=a0.x; A2[1]=a0.y; A2[2]=a0.z; A2[3]=a0.w;
    }

    if (!isCol) {
        float ef[NH], eb[NH], Pp[NH];
        #pragma unroll
        for (int n = 0; n < NH; n++) { ef[n]=0.f; eb[n]=0.f; Pp[n]=1.f; }
        float rs = 0.f;
        #pragma unroll 4
        for (int ts = 0; ts < 64; ts++) {
            int p = chunk*64 + ts;
            size_t idx = ((size_t)(b*LL + p))*CC + c;
            float2 du = g_du[idx];
            float d = du.x, uu = du.y;
            rs += d;
            float4 v = g_Bm4[(b*LL + p)*4 + q];
            float bm[NH] = {v.x, v.y, v.z, v.w};
            #pragma unroll
            for (int n = 0; n < NH; n++) {
                float a = ex2f(d * A2[n]);
                float w = uu * bm[n];
                eb[n] = fmaf(w, Pp[n], eb[n]);
                Pp[n] *= a;
                ef[n] = fmaf(a, ef[n], w);
            }
        }
        int i4 = ((b*RR + chunk)*CC + c)*4 + q;
        g_ef4[i4] = make_float4(ef[0],ef[1],ef[2],ef[3]);
        g_eb4[i4] = make_float4(eb[0],eb[1],eb[2],eb[3]);
        if (q == 0) g_rs[(b*RR + chunk)*CC + c] = rs;
    } else {
        float ec[NH];
        #pragma unroll
        for (int n = 0; n < NH; n++) ec[n] = 0.f;
        float cs = 0.f;
        #pragma unroll 4
        for (int h = 0; h < 64; h++) {
            int p = h*64 + chunk;
            size_t idx = ((size_t)(b*LL + p))*CC + c;
            float2 du = g_du[idx];
            float d = du.x, uu = du.y;
            cs += d;
            float4 v = g_Bm4[(b*LL + p)*4 + q];
            float bm[NH] = {v.x, v.y, v.z, v.w};
            #pragma unroll
            for (int n = 0; n < NH; n++) {
                float a = ex2f(d * A2[n]);
                float wv = uu * bm[n];
                ec[n] = fmaf(a, ec[n], wv);
            }
        }
        int i4 = ((b*RR + chunk)*CC + c)*4 + q;
        g_ec4[i4] = make_float4(ec[0],ec[1],ec[2],ec[3]);
        if (q == 0) g_cs[(b*RR + chunk)*CC + c] = cs;
    }
}

// ---------------- mid: inter-chunk carry scans, 3-way parallel ----------------
__global__ void k_mid() {
    int g = blockIdx.x * blockDim.x + threadIdx.x;   // BB*CC*NN = 8192
    int which = blockIdx.y;                           // 0: dir1, 1: dir2+3, 2: dir4
    int b = g / (CC*NN);
    int cn = g % (CC*NN);
    int c = cn / NN;
    float A2 = ((const float*)g_A4)[cn];
    const float* gef = (const float*)g_ef4;
    const float* geb = (const float*)g_eb4;
    const float* gec = (const float*)g_ec4;
    float* gc1 = (float*)g_c14;
    float* gc2 = (float*)g_c24;
    float* gc3 = (float*)g_c34;
    float* gc4 = (float*)g_c44;
    size_t ebase = (size_t)b*RR*CC*NN + cn;
    int rbase = b*RR*CC + c;

    if (which == 0) {
        float cur = 0.f;
        for (int r = 0; r < RR; r++) {
            size_t ei = ebase + (size_t)r*CC*NN;
            gc1[ei] = cur;
            float G = ex2f(A2 * g_rs[rbase + r*CC]);
            cur = fmaf(G, cur, gef[ei]);
        }
    } else if (which == 1) {
        float cur2 = 0.f, cur3 = 0.f;
        for (int r = RR-1; r >= 0; r--) {
            size_t ei = ebase + (size_t)r*CC*NN;
            gc2[ei] = cur2;
            gc3[ei] = cur3;
            float G = ex2f(A2 * g_rs[rbase + r*CC]);
            cur2 = fmaf(G, cur2, geb[ei]);
            cur3 = fmaf(G, cur3, gef[ei]);
        }
    } else {
        float cur4 = 0.f;
        for (int w = RR-1; w >= 0; w--) {
            size_t ei = ebase + (size_t)w*CC*NN;
            gc4[ei] = cur4;
            float G = ex2f(A2 * g_cs[rbase + w*CC]);
            cur4 = fmaf(G, cur4, gec[ei]);
        }
    }
}

// ---------------- pass2: local scans with carries, emit y ----------------
__global__ void __launch_bounds__(256) k_pass2() {
    int blk = blockIdx.x;
    bool isCol = blk >= BB*RR*4;
    int bid = isCol ? blk - BB*RR*4 : blk;
    int b = bid / (RR*4);
    int rem = bid % (RR*4);
    int chunk = rem >> 2;
    int cg = rem & 3;
    int q = threadIdx.x & 3;
    int c = cg*64 + (threadIdx.x >> 2);

    float A2[NH];
    {
        float4 a0 = g_A4[c*4 + q];
        A2[0]=a0.x; A2[1]=a0.y; A2[2]=a0.z; A2[3]=a0.w;
    }
    int i4 = ((b*RR + chunk)*CC + c)*4 + q;

    if (!isCol) {
        float h1[NH], h3[NH];
        {
            float4 v0 = g_c14[i4];
            h1[0]=v0.x; h1[1]=v0.y; h1[2]=v0.z; h1[3]=v0.w;
            float4 w0 = g_c34[i4];
            h3[0]=w0.x; h3[1]=w0.y; h3[2]=w0.z; h3[3]=w0.w;
        }
        #pragma unroll 4
        for (int ts = 0; ts < 64; ts++) {
            int p = chunk*64 + ts;
            size_t idx = ((size_t)(b*LL + p))*CC + c;
            float2 du = g_du[idx];
            float d = du.x, uu = du.y;
            float4 v = g_Bm4[(b*LL + p)*4 + q];
            float bm[NH] = {v.x, v.y, v.z, v.w};
            float4 u = g_Cm4[(b*LL + p)*4 + q];
            float cm[NH] = {u.x, u.y, u.z, u.w};
            float y = 0.f;
            #pragma unroll
            for (int n = 0; n < NH; n++) {
                float a = ex2f(d * A2[n]);
                float w = uu * bm[n];
                h1[n] = fmaf(a, h1[n], w);
                h3[n] = fmaf(a, h3[n], w);
                y = fmaf(h1[n] + h3[n], cm[n], y);
            }
            y += __shfl_xor_sync(0xffffffffu, y, 1);
            y += __shfl_xor_sync(0xffffffffu, y, 2);
            if (q == 0) g_y13[idx] = y;
        }
        float h2[NH];
        {
            float4 v0 = g_c24[i4];
            h2[0]=v0.x; h2[1]=v0.y; h2[2]=v0.z; h2[3]=v0.w;
        }
        #pragma unroll 4
        for (int ts = 63; ts >= 0; ts--) {
            int p = chunk*64 + ts;
            size_t idx = ((size_t)(b*LL + p))*CC + c;
            float2 du = g_du[idx];
            float d = du.x, uu = du.y;
            float4 v = g_Bm4[(b*LL + p)*4 + q];
            float bm[NH] = {v.x, v.y, v.z, v.w};
            float4 u = g_Cm4[(b*LL + p)*4 + q];
            float cm[NH] = {u.x, u.y, u.z, u.w};
            float y = 0.f;
            #pragma unroll
            for (int n = 0; n < NH; n++) {
                float a = ex2f(d * A2[n]);
                float w = uu * bm[n];
                h2[n] = fmaf(a, h2[n], w);
                y = fmaf(h2[n], cm[n], y);
            }
            y += __shfl_xor_sync(0xffffffffu, y, 1);
            y += __shfl_xor_sync(0xffffffffu, y, 2);
            if (q == 0) g_y13[idx] += y;
        }
    } else {
        float h4[NH];
        {
            float4 v0 = g_c44[i4];
            h4[0]=v0.x; h4[1]=v0.y; h4[2]=v0.z; h4[3]=v0.w;
        }
        #pragma unroll 4
        for (int h = 0; h < 64; h++) {
            int p = h*64 + chunk;
            size_t idx = ((size_t)(b*LL + p))*CC + c;
            float2 du = g_du[idx];
            float d = du.x, uu = du.y;
            float4 v = g_Bm4[(b*LL + p)*4 + q];
            float bm[NH] = {v.x, v.y, v.z, v.w};
            float4 u = g_Cm4[(b*LL + p)*4 + q];
            float cm[NH] = {u.x, u.y, u.z, u.w};
            float y = 0.f;
            #pragma unroll
            for (int n = 0; n < NH; n++) {
                float a = ex2f(d * A2[n]);
                float wv = uu * bm[n];
                h4[n] = fmaf(a, h4[n], wv);
                y = fmaf(h4[n], cm[n], y);
            }
            y += __shfl_xor_sync(0xffffffffu, y, 1);
            y += __shfl_xor_sync(0xffffffffu, y, 2);
            if (q == 0) g_y4[idx] = y;
        }
    }
}

// ---------------- final: combine, add x*D, transpose (p,c) -> (c,p) ----------------
__global__ void k_final(const float* __restrict__ F,
                        const float* __restrict__ Dv,
                        float* __restrict__ out)
{
    __shared__ float tile[32][33];
    int p0 = blockIdx.x * 32;
    int c0 = blockIdx.y * 32;
    int b = blockIdx.z;
    int tx = threadIdx.x, ty = threadIdx.y;   // (32, 8)
    #pragma unroll
    for (int i = 0; i < 4; i++) {
        int p = p0 + ty + i*8;
        size_t idx = ((size_t)(b*LL + p))*CC + c0 + tx;
        tile[ty + i*8][tx] = g_y13[idx] + g_y4[idx];
    }
    __syncthreads();
    #pragma unroll
    for (int i = 0; i < 4; i++) {
        int cc = c0 + ty + i*8;
        int p = p0 + tx;
        size_t o = (size_t)b*CC*LL + (size_t)cc*LL + p;
        out[o] = 0.25f * tile[tx][ty + i*8] + F[o] * Dv[cc];
    }
}

// ---------------- launch ----------------
extern "C" void kernel_launch(void* const* d_in, const int* in_sizes, int n_in,
                              void* d_out, int out_size) {
    const float* F     = (const float*)d_in[0];
    const float* A_log = (const float*)d_in[1];
    const float* Dv    = (const float*)d_in[2];
    const float* Wd    = (const float*)d_in[3];
    const float* bd    = (const float*)d_in[4];
    const float* WB    = (const float*)d_in[5];
    const float* WC    = (const float*)d_in[6];
    float* out = (float*)d_out;

    k_gemm_bc<<<BB*LL/64, 256>>>(F, WB, WC, A_log);
    {
        dim3 gd(BB*LL/128, CC/64);
        k_gemm_delta_tc<<<gd, 256>>>(F, Wd, bd);
    }
    k_pass1<<<2*BB*RR*4, 256>>>();
    k_mid<<<dim3(BB*CC*NN/256, 3), 256>>>();
    k_pass2<<<2*BB*RR*4, 256>>>();
    k_final<<<dim3(LL/32, CC/32, BB), dim3(32, 8)>>>(F, Dv, out);
}